// round 2
// baseline (speedup 1.0000x reference)
#include <cuda_runtime.h>
#include <math.h>

#define NMAX 50000
#define EMAX 200000
#define ETMAX (NMAX + EMAX)

// ---------------- scratch (device globals; no allocations allowed) ----------
__device__ float g_h1[(size_t)NMAX * 1024];   // layer1 GEMM out  [N,8,128]
__device__ float g_a1[(size_t)NMAX * 1024];   // layer1 attn agg  [N,1024]
__device__ float g_h2[(size_t)NMAX * 128];
__device__ float g_a2[(size_t)NMAX * 128];
__device__ float g_h3[(size_t)NMAX * 64];
__device__ float g_a3[(size_t)NMAX * 64];
__device__ float g_es[(size_t)NMAX * 8];
__device__ float g_ed[(size_t)NMAX * 8];
__device__ float g_z [(size_t)NMAX * 8];
__device__ float g_w [(size_t)ETMAX * 8];
__device__ int   g_src[ETMAX];
__device__ int   g_dst[ETMAX];
__device__ int   g_is64;

// ---------------- edge-index dtype probe ------------------------------------
__global__ void detect_dtype(const void* ei, int N) {
    if (blockIdx.x == 0 && threadIdx.x == 0) {
        const long long* p = (const long long*)ei;
        int ok = 1;
        for (int i = 0; i < 64; i++) {
            long long v = p[i];
            if (v < 0 || v >= (long long)N) { ok = 0; break; }
        }
        g_is64 = ok;
    }
}

__global__ void prep_edges(const void* ei, int E, int ET) {
    int i = blockIdx.x * blockDim.x + threadIdx.x;
    if (i >= ET) return;
    int s, d;
    if (i < E) {
        if (g_is64) {
            const long long* p = (const long long*)ei;
            s = (int)p[i]; d = (int)p[E + i];
        } else {
            const int* p = (const int*)ei;
            s = p[i]; d = p[E + i];
        }
    } else {
        s = d = i - E;  // self loop
    }
    g_src[i] = s;
    g_dst[i] = d;
}

// ---------------- fp32 tiled GEMM: C[M,N] = A[M,K] @ B[K,N] -----------------
__global__ void gemm_tiled(const float* __restrict__ A, const float* __restrict__ B,
                           float* __restrict__ C, int M, int N, int K) {
    __shared__ float As[16][65];
    __shared__ float Bs[16][64];
    const int tid = threadIdx.x;
    const int tx = tid & 15, ty = tid >> 4;
    const int rowBase = blockIdx.y * 64, colBase = blockIdx.x * 64;
    float acc[4][4] = {};
    for (int k0 = 0; k0 < K; k0 += 16) {
        #pragma unroll
        for (int l = 0; l < 4; l++) {
            int lin = tid + 256 * l;
            int kk = lin & 15, m = lin >> 4;
            int r = rowBase + m, k = k0 + kk;
            As[kk][m] = (r < M && k < K) ? A[(size_t)r * K + k] : 0.f;
        }
        #pragma unroll
        for (int l = 0; l < 4; l++) {
            int lin = tid + 256 * l;
            int n = lin & 63, kk = lin >> 6;
            int k = k0 + kk, c = colBase + n;
            Bs[kk][n] = (k < K && c < N) ? B[(size_t)k * N + c] : 0.f;
        }
        __syncthreads();
        #pragma unroll
        for (int kk = 0; kk < 16; kk++) {
            float a[4], b[4];
            #pragma unroll
            for (int i = 0; i < 4; i++) a[i] = As[kk][ty * 4 + i];
            #pragma unroll
            for (int j = 0; j < 4; j++) b[j] = Bs[kk][tx * 4 + j];
            #pragma unroll
            for (int i = 0; i < 4; i++)
                #pragma unroll
                for (int j = 0; j < 4; j++)
                    acc[i][j] = fmaf(a[i], b[j], acc[i][j]);
        }
        __syncthreads();
    }
    #pragma unroll
    for (int i = 0; i < 4; i++) {
        int r = rowBase + ty * 4 + i;
        if (r >= M) continue;
        #pragma unroll
        for (int j = 0; j < 4; j++) {
            int c = colBase + tx * 4 + j;
            if (c < N) C[(size_t)r * N + c] = acc[i][j];
        }
    }
}

// ---------------- per-node attention scores ---------------------------------
// NOTE: es/ed pointers are DEVICE addresses obtained via cudaGetSymbolAddress.
__global__ void attn_scores(const float* __restrict__ h, const float* __restrict__ asrc,
                            const float* __restrict__ adst, float* __restrict__ es,
                            float* __restrict__ ed, int N, int H, int C) {
    int wid = (blockIdx.x * blockDim.x + threadIdx.x) >> 5;
    int lane = threadIdx.x & 31;
    if (wid >= N * H) return;
    int n = wid / H, hh = wid - n * H;
    const float* hp = h + (size_t)n * H * C + (size_t)hh * C;
    float s1 = 0.f, s2 = 0.f;
    for (int c = lane; c < C; c += 32) {
        float v = hp[c];
        s1 += v * asrc[hh * C + c];
        s2 += v * adst[hh * C + c];
    }
    #pragma unroll
    for (int o = 16; o; o >>= 1) {
        s1 += __shfl_down_sync(0xffffffff, s1, o);
        s2 += __shfl_down_sync(0xffffffff, s2, o);
    }
    if (lane == 0) { es[wid] = s1; ed[wid] = s2; }
}

// ---------------- edge logits + softmax denominator -------------------------
__global__ void edge_scores(int ET, int H) {
    int t = blockIdx.x * blockDim.x + threadIdx.x;
    if (t >= ET * H) return;
    int eid = t / H, hh = t - eid * H;
    float e = g_es[g_src[eid] * H + hh] + g_ed[g_dst[eid] * H + hh];
    e = e > 0.f ? e : 0.2f * e;            // leaky_relu(0.2)
    float we = expf(e);                    // no-max softmax (logits are O(10))
    g_w[t] = we;
    atomicAdd(&g_z[g_dst[eid] * H + hh], we);
}

// ---------------- weighted scatter aggregation ------------------------------
__global__ void aggregate(const float* __restrict__ h, float* __restrict__ out,
                          int ET, int H, int C) {
    int wid = (blockIdx.x * blockDim.x + threadIdx.x) >> 5;
    int lane = threadIdx.x & 31;
    if (wid >= ET * H) return;
    int eid = wid / H, hh = wid - eid * H;
    int s = g_src[eid], d = g_dst[eid];
    float alpha = g_w[wid] / (g_z[d * H + hh] + 1e-16f);
    const float* hp = h + (size_t)s * H * C + (size_t)hh * C;
    float* op = out + (size_t)d * H * C + (size_t)hh * C;
    for (int c = lane; c < C; c += 32)
        atomicAdd(&op[c], alpha * hp[c]);
}

// ---------------- bias + ELU (in place) -------------------------------------
__global__ void bias_elu(float* __restrict__ x, const float* __restrict__ b,
                         int total, int HC) {
    int i = blockIdx.x * blockDim.x + threadIdx.x;
    if (i >= total) return;
    float v = x[i] + b[i % HC];
    x[i] = v > 0.f ? v : expm1f(v);
}

// ---------------- risk head: sigmoid(h @ Wr + br) ---------------------------
__global__ void risk_head(const float* __restrict__ h, const float* __restrict__ Wr,
                          const float* __restrict__ br, float* __restrict__ out, int N) {
    int wid = (blockIdx.x * blockDim.x + threadIdx.x) >> 5;
    int lane = threadIdx.x & 31;
    if (wid >= N) return;
    float s = 0.f;
    #pragma unroll
    for (int c = lane; c < 64; c += 32)
        s += h[(size_t)wid * 64 + c] * Wr[c];
    #pragma unroll
    for (int o = 16; o; o >>= 1)
        s += __shfl_down_sync(0xffffffff, s, o);
    if (lane == 0) out[wid] = 1.f / (1.f + expf(-(s + br[0])));
}

// ---------------- launch ----------------------------------------------------
extern "C" void kernel_launch(void* const* d_in, const int* in_sizes, int n_in,
                              void* d_out, int out_size) {
    const float* x   = (const float*)d_in[0];
    const void*  ei  = d_in[1];
    const float* W1  = (const float*)d_in[2];
    const float* as1 = (const float*)d_in[3];
    const float* ad1 = (const float*)d_in[4];
    const float* b1  = (const float*)d_in[5];
    const float* W2  = (const float*)d_in[6];
    const float* as2 = (const float*)d_in[7];
    const float* ad2 = (const float*)d_in[8];
    const float* b2  = (const float*)d_in[9];
    const float* W3  = (const float*)d_in[10];
    const float* as3 = (const float*)d_in[11];
    const float* ad3 = (const float*)d_in[12];
    const float* b3  = (const float*)d_in[13];
    const float* Wr  = (const float*)d_in[14];
    const float* br  = (const float*)d_in[15];

    const int N  = in_sizes[0] / 66;
    const int E  = in_sizes[1] / 2;
    const int ET = E + N;

    // All device-global addresses used as KERNEL ARGUMENTS must come from
    // cudaGetSymbolAddress (host-side symbol names give host shadow addresses,
    // which HMM silently accepts -> the round-1 bug).
    void *p_h1, *p_a1, *p_h2, *p_a2, *p_h3, *p_a3, *p_z, *p_es, *p_ed;
    cudaGetSymbolAddress(&p_h1, g_h1);
    cudaGetSymbolAddress(&p_a1, g_a1);
    cudaGetSymbolAddress(&p_h2, g_h2);
    cudaGetSymbolAddress(&p_a2, g_a2);
    cudaGetSymbolAddress(&p_h3, g_h3);
    cudaGetSymbolAddress(&p_a3, g_a3);
    cudaGetSymbolAddress(&p_z,  g_z);
    cudaGetSymbolAddress(&p_es, g_es);
    cudaGetSymbolAddress(&p_ed, g_ed);

    float* h1 = (float*)p_h1; float* a1 = (float*)p_a1;
    float* h2 = (float*)p_h2; float* a2 = (float*)p_a2;
    float* h3 = (float*)p_h3; float* a3 = (float*)p_a3;
    float* es = (float*)p_es; float* ed = (float*)p_ed;

    // edges
    detect_dtype<<<1, 32>>>(ei, N);
    prep_edges<<<(ET + 255) / 256, 256>>>(ei, E, ET);

    // ---------------- layer 1: 66 -> 8x128, concat -------------------------
    cudaMemsetAsync(p_a1, 0, (size_t)N * 1024 * sizeof(float));
    cudaMemsetAsync(p_z,  0, (size_t)N * 8 * sizeof(float));
    {
        dim3 g((1024 + 63) / 64, (N + 63) / 64);
        gemm_tiled<<<g, 256>>>(x, W1, h1, N, 1024, 66);
    }
    attn_scores<<<(N * 8 + 7) / 8, 256>>>(h1, as1, ad1, es, ed, N, 8, 128);
    edge_scores<<<(ET * 8 + 255) / 256, 256>>>(ET, 8);
    aggregate<<<(ET * 8 + 7) / 8, 256>>>(h1, a1, ET, 8, 128);
    bias_elu<<<((N * 1024) + 255) / 256, 256>>>(a1, b1, N * 1024, 1024);

    // ---------------- layer 2: 1024 -> 128, 1 head --------------------------
    cudaMemsetAsync(p_a2, 0, (size_t)N * 128 * sizeof(float));
    cudaMemsetAsync(p_z,  0, (size_t)N * 8 * sizeof(float));
    {
        dim3 g((128 + 63) / 64, (N + 63) / 64);
        gemm_tiled<<<g, 256>>>(a1, W2, h2, N, 128, 1024);
    }
    attn_scores<<<(N + 7) / 8, 256>>>(h2, as2, ad2, es, ed, N, 1, 128);
    edge_scores<<<(ET + 255) / 256, 256>>>(ET, 1);
    aggregate<<<(ET + 7) / 8, 256>>>(h2, a2, ET, 1, 128);
    bias_elu<<<((N * 128) + 255) / 256, 256>>>(a2, b2, N * 128, 128);

    // ---------------- layer 3: 128 -> 64, 1 head ----------------------------
    cudaMemsetAsync(p_a3, 0, (size_t)N * 64 * sizeof(float));
    cudaMemsetAsync(p_z,  0, (size_t)N * 8 * sizeof(float));
    {
        dim3 g((64 + 63) / 64, (N + 63) / 64);
        gemm_tiled<<<g, 256>>>(a2, W3, h3, N, 64, 128);
    }
    attn_scores<<<(N + 7) / 8, 256>>>(h3, as3, ad3, es, ed, N, 1, 64);
    edge_scores<<<(ET + 255) / 256, 256>>>(ET, 1);
    aggregate<<<(ET + 7) / 8, 256>>>(h3, a3, ET, 1, 64);
    bias_elu<<<((N * 64) + 255) / 256, 256>>>(a3, b3, N * 64, 64);

    // ---------------- risk head ---------------------------------------------
    risk_head<<<(N + 7) / 8, 256>>>(a3, Wr, br, (float*)d_out, N);
}